// round 1
// baseline (speedup 1.0000x reference)
#include <cuda_runtime.h>
#include <cstdint>

#define B_    32
#define C_    128
#define L_    4096
#define P_    100
#define Q_    20
#define NBIN  21

#define LCHUNK 256              // l-range per block
#define LSUB   64               // l sub-tile
#define NSUB   (LCHUNK / LSUB)  // 4
#define WS_STRIDE 104           // P padded to 104 (multiple of 8, keeps LDS.128 aligned)

#define COUNTS_N (B_ * P_ * NBIN)   // 67200
#define WT_N     (C_ * WS_STRIDE)   // 13312

// Scratch in device globals (no runtime allocation allowed).
__device__ int   g_counts[COUNTS_N];
__device__ float g_Wt[WT_N];        // Wt[c][p], p-padded with zeros

// Dynamic shared layout:
//   float Ws[128][104]   (53248 B)
//   float Xs[128][64]    (32768 B)
//   int   hist[100*21]   ( 8400 B)
#define SMEM_BYTES ((C_ * WS_STRIDE + C_ * LSUB) * 4 + P_ * NBIN * 4)

#define FFMA2(d, a, b) \
    asm("fma.rn.f32x2 %0, %1, %2, %0;" : "+l"(d) : "l"(a), "l"(b))

#define PACK2(d, s) \
    asm("mov.b64 %0, {%1, %1};" : "=l"(d) : "f"(s))

// ---------------------------------------------------------------------------
// Prep: zero histogram counts, build transposed zero-padded weight matrix.
// ---------------------------------------------------------------------------
__global__ void prep_kernel(const float* __restrict__ W) {
    int i = blockIdx.x * blockDim.x + threadIdx.x;
    if (i < COUNTS_N) g_counts[i] = 0;
    if (i < WT_N) {
        int c = i / WS_STRIDE;
        int p = i % WS_STRIDE;
        g_Wt[i] = (p < P_) ? W[p * C_ + c] : 0.0f;
    }
}

// ---------------------------------------------------------------------------
// Main: projection GEMM (register-tiled, packed f32x2 FMA) + binning.
// Block: one (batch b, 256-wide l-chunk). 256 threads = 16 p-cols x 16 l-rows.
// Thread tile: 4 l x 8 p. Only p-columns 0..12 carry real projections.
// ---------------------------------------------------------------------------
extern __shared__ __align__(16) float smem[];

__global__ __launch_bounds__(256, 2)
void radon_main(const float* __restrict__ X,
                const float* __restrict__ minv,
                const float* __restrict__ maxv) {
    float* Ws  = smem;                              // [128][104]
    float* Xs  = smem + C_ * WS_STRIDE;             // [128][64]
    int*   hist = (int*)(smem + C_ * WS_STRIDE + C_ * LSUB);  // [100*21]

    const int tid = threadIdx.x;
    const int b   = blockIdx.x >> 4;
    const int l0  = (blockIdx.x & 15) * LCHUNK;

    // Zero shared histogram.
    for (int i = tid; i < P_ * NBIN; i += 256) hist[i] = 0;

    // Stage Wt into shared (coalesced float4, conflict-free stores).
    for (int i = tid; i < WT_N / 4; i += 256) {
        ((float4*)Ws)[i] = ((const float4*)g_Wt)[i];
    }

    const int pcol  = tid >> 4;       // 0..15
    const int lrow  = tid & 15;       // 0..15
    const int pbase = pcol * 8;
    const bool active = (pbase < P_); // p-columns 0..12

    // Per-thread threshold params for up to 8 projections.
    float pmin[8], pscl[8];
    if (active) {
#pragma unroll
        for (int j = 0; j < 8; j++) {
            int p = pbase + j;
            if (p < P_) {
                float mn = minv[p], mx = maxv[p];
                pmin[j] = mn;
                pscl[j] = 21.0f / (mx - mn);
            } else {
                pmin[j] = 0.0f;
                pscl[j] = 0.0f;
            }
        }
    }

    const float* Xb = X + (size_t)b * C_ * L_ + l0;

    for (int ls = 0; ls < NSUB; ls++) {
        __syncthreads();  // Ws/hist ready (iter 0) or previous compute done

        // Load X sub-tile: Xs[c][0..63], coalesced float4.
        for (int idx = tid; idx < (C_ * LSUB) / 4; idx += 256) {
            int c  = idx >> 4;         // /16 float4 per row
            int lq = idx & 15;
            float4 v = *(const float4*)(Xb + c * L_ + ls * LSUB + lq * 4);
            *(float4*)(Xs + c * LSUB + lq * 4) = v;
        }
        __syncthreads();

        if (active) {
            // Accumulators: 4 l x 4 p-pairs, packed f32x2.
            unsigned long long acc[4][4];
#pragma unroll
            for (int i = 0; i < 4; i++)
#pragma unroll
                for (int j = 0; j < 4; j++) acc[i][j] = 0ull;

#pragma unroll 4
            for (int k = 0; k < C_; k++) {
                float4 xv = *(const float4*)(Xs + k * LSUB + (lrow << 2));
                const float* wrow = Ws + k * WS_STRIDE + pbase;
                ulonglong2 wA = *(const ulonglong2*)(wrow);
                ulonglong2 wB = *(const ulonglong2*)(wrow + 4);

                unsigned long long xx0, xx1, xx2, xx3;
                PACK2(xx0, xv.x);
                PACK2(xx1, xv.y);
                PACK2(xx2, xv.z);
                PACK2(xx3, xv.w);

                FFMA2(acc[0][0], xx0, wA.x); FFMA2(acc[0][1], xx0, wA.y);
                FFMA2(acc[0][2], xx0, wB.x); FFMA2(acc[0][3], xx0, wB.y);
                FFMA2(acc[1][0], xx1, wA.x); FFMA2(acc[1][1], xx1, wA.y);
                FFMA2(acc[1][2], xx1, wB.x); FFMA2(acc[1][3], xx1, wB.y);
                FFMA2(acc[2][0], xx2, wA.x); FFMA2(acc[2][1], xx2, wA.y);
                FFMA2(acc[2][2], xx2, wB.x); FFMA2(acc[2][3], xx2, wB.y);
                FFMA2(acc[3][0], xx3, wA.x); FFMA2(acc[3][1], xx3, wA.y);
                FFMA2(acc[3][2], xx3, wB.x); FFMA2(acc[3][3], xx3, wB.y);
            }

            // Bin: j = clamp(floor((a - min_p) * 21/(max_p - min_p)), 0, 20).
            // cdf[q] (q=1..20) = (1/L) * sum_{j<q} hist[j].
#pragma unroll
            for (int i = 0; i < 4; i++) {
#pragma unroll
                for (int jp = 0; jp < 4; jp++) {
                    unsigned long long v = acc[i][jp];
                    float a0 = __uint_as_float((unsigned)v);
                    float a1 = __uint_as_float((unsigned)(v >> 32));
                    int p0 = pbase + 2 * jp;
                    if (p0 < P_) {
                        int bin = __float2int_rd((a0 - pmin[2 * jp]) * pscl[2 * jp]);
                        bin = max(0, min(bin, 20));
                        atomicAdd(&hist[p0 * NBIN + bin], 1);
                    }
                    if (p0 + 1 < P_) {
                        int bin = __float2int_rd((a1 - pmin[2 * jp + 1]) * pscl[2 * jp + 1]);
                        bin = max(0, min(bin, 20));
                        atomicAdd(&hist[(p0 + 1) * NBIN + bin], 1);
                    }
                }
            }
        }
    }

    __syncthreads();
    // Flush block histogram to global counts.
    for (int i = tid; i < P_ * NBIN; i += 256) {
        int h = hist[i];
        if (h) atomicAdd(&g_counts[b * P_ * NBIN + i], h);
    }
}

// ---------------------------------------------------------------------------
// Finalize: prefix-sum the 21 bins per (b,p) -> 20 cdf values.
// ---------------------------------------------------------------------------
__global__ void finalize_kernel(float* __restrict__ out) {
    int id = blockIdx.x * blockDim.x + threadIdx.x;
    if (id >= B_ * P_) return;
    int b = id / P_;
    int p = id % P_;
    const int* h = &g_counts[(b * P_ + p) * NBIN];
    const float inv = 1.0f / (float)L_;
    int run = 0;
#pragma unroll
    for (int q = 0; q < Q_; q++) {
        run += h[q];
        out[(size_t)b * (P_ * Q_) + p * Q_ + q] = (float)run * inv;
    }
}

// ---------------------------------------------------------------------------
extern "C" void kernel_launch(void* const* d_in, const int* in_sizes, int n_in,
                              void* d_out, int out_size) {
    const float* X    = (const float*)d_in[0];   // [B, C, L]
    const float* W    = (const float*)d_in[1];   // [P, C]
    const float* minv = (const float*)d_in[2];   // [P]
    const float* maxv = (const float*)d_in[3];   // [P]
    float* out = (float*)d_out;                  // [B, P*Q]

    cudaFuncSetAttribute(radon_main,
                         cudaFuncAttributeMaxDynamicSharedMemorySize,
                         SMEM_BYTES);

    prep_kernel<<<(COUNTS_N + 255) / 256, 256>>>(W);
    radon_main<<<B_ * 16, 256, SMEM_BYTES>>>(X, minv, maxv);
    finalize_kernel<<<(B_ * P_ + 255) / 256, 256>>>(out);
}

// round 4
// speedup vs baseline: 1.7910x; 1.7910x over previous
#include <cuda_runtime.h>
#include <cuda_bf16.h>
#include <cstdint>

#define B_   32
#define C_   128
#define L_   4096
#define P_   100
#define Q_   20
#define LC   128
#define NLC  (L_ / LC)   // 32
#define PT   8           // p-tiles of 16 (P padded to 128)

#define SM_XH   0
#define SM_XL   32768
#define SM_TBL  65536
#define SM_TOTAL (65536 + 441 * 32)   // 79648

// W packed in mma-A fragment order: [ptile][kstep][hi/lo][lane] uint4
__device__ uint4 g_Wfrag[PT * 8 * 2 * 32];
// chunk scratch: [b][p(128)][w5(5)][lc(32)] packed byte counters
__device__ unsigned g_chunk[B_ * 128 * 5 * NLC];

__device__ __forceinline__ unsigned smem_u32(const void* p) {
    unsigned a;
    asm("{ .reg .u64 t; cvta.to.shared.u64 t, %1; cvt.u32.u64 %0, t; }" : "=r"(a) : "l"(p));
    return a;
}
#define LDSM_T(r0, r1, r2, r3, a) \
    asm volatile("ldmatrix.sync.aligned.m8n8.x4.trans.shared.b16 {%0,%1,%2,%3}, [%4];" \
                 : "=r"(r0), "=r"(r1), "=r"(r2), "=r"(r3) : "r"(a))
#define MMA_BF16(Cv, Af, b0_, b1_) \
    asm volatile("mma.sync.aligned.m16n8k16.row.col.f32.bf16.bf16.f32 " \
                 "{%0,%1,%2,%3}, {%4,%5,%6,%7}, {%8,%9}, {%0,%1,%2,%3};" \
                 : "+f"((Cv)[0]), "+f"((Cv)[1]), "+f"((Cv)[2]), "+f"((Cv)[3]) \
                 : "r"((Af).x), "r"((Af).y), "r"((Af).z), "r"((Af).w), "r"(b0_), "r"(b1_))

// floor((a-mn)*s) clamped to [0,20] via magic-add (no F2I)
__device__ __forceinline__ unsigned bin_of(float a, float s, float bc) {
    float g = fminf(fmaxf(fmaf(a, s, bc), -0.5f), 19.99f);
    return __float_as_uint(__fadd_rn(g, 12582912.0f)) & 63u;
}

// ---------------------------------------------------------------------------
__global__ void prep_kernel(const float* __restrict__ W) {
    int i = blockIdx.x * 256 + threadIdx.x;
    if (i >= PT * 8 * 2 * 32 * 4) return;
    int r = i & 3, lane = (i >> 2) & 31, h = (i >> 7) & 1, s = (i >> 8) & 7, t = i >> 11;
    int row = t * 16 + (lane >> 2) + (r & 1) * 8;
    int kp  = s * 16 + 2 * (lane & 3) + (r >> 1) * 8;
    unsigned val = 0;
    if (row < P_) {
        float w0 = W[row * C_ + kp], w1 = W[row * C_ + kp + 1];
        unsigned u0 = __float_as_uint(w0), u1 = __float_as_uint(w1);
        if (h == 0) {
            val = __byte_perm(u0, u1, 0x7632);          // truncated bf16 hi
        } else {
            float l0 = w0 - __uint_as_float(u0 & 0xFFFF0000u);
            float l1 = w1 - __uint_as_float(u1 & 0xFFFF0000u);
            __nv_bfloat162 p2 = __float22bfloat162_rn(make_float2(l0, l1));
            val = *(unsigned*)&p2;
        }
    }
    ((unsigned*)g_Wfrag)[i] = val;
}

// ---------------------------------------------------------------------------
extern __shared__ __align__(16) char smem[];

__global__ __launch_bounds__(256, 2)
void radon_hmma(const float* __restrict__ X,
                const float* __restrict__ minv,
                const float* __restrict__ maxv) {
    const int tid = threadIdx.x, w = tid >> 5, lane = tid & 31;
    const int b = blockIdx.x >> 5, lc = blockIdx.x & 31;
    const unsigned sXh = smem_u32(smem) + SM_XH;
    const unsigned sXl = smem_u32(smem) + SM_XL;
    unsigned* tbl = (unsigned*)(smem + SM_TBL);

    // pair table: tbl[j1*21+j2][w5] bytes(q=4w5+b4) = (q>=j1)+(q>=j2); stride 8 words
    for (int i = tid; i < 441 * 8; i += 256) {
        int row = i >> 3, w5 = i & 7;
        int j1 = row / 21, j2 = row % 21;
        unsigned v = 0;
        if (w5 < 5) {
#pragma unroll
            for (int b4 = 0; b4 < 4; b4++) {
                int q = 4 * w5 + b4;
                if (q < Q_) v |= (unsigned)((q >= j1) + (q >= j2)) << (8 * b4);
            }
        }
        tbl[i] = v;
    }

    uint4 Ahi[8], Alo[8];
#pragma unroll
    for (int s = 0; s < 8; s++) {
        Ahi[s] = g_Wfrag[((w * 8 + s) * 2 + 0) * 32 + lane];
        Alo[s] = g_Wfrag[((w * 8 + s) * 2 + 1) * 32 + lane];
    }

    const int p0 = w * 16 + (lane >> 2), p1 = p0 + 8;
    float s0 = 0.f, c0b = 0.f, s1 = 0.f, c1b = 0.f;
    if (p0 < P_) { float mn = minv[p0]; s0 = 21.0f / (maxv[p0] - mn); c0b = -mn * s0 - 0.5f; }
    if (p1 < P_) { float mn = minv[p1]; s1 = 21.0f / (maxv[p1] - mn); c1b = -mn * s1 - 0.5f; }

    // convert X chunk -> bf16 hi/lo, [c][l] rows (256B), 16B XOR swizzle
    const float* Xb = X + (size_t)b * C_ * L_ + lc * LC;
#pragma unroll 4
    for (int it = 0; it < 16; it++) {
        int lin = it * 256 + tid;
        int c = lin >> 5, l4 = lin & 31;
        float4 v = *(const float4*)(Xb + (size_t)c * L_ + 4 * l4);
        unsigned u0 = __float_as_uint(v.x), u1 = __float_as_uint(v.y);
        unsigned u2 = __float_as_uint(v.z), u3 = __float_as_uint(v.w);
        uint2 hi, lo;
        hi.x = __byte_perm(u0, u1, 0x7632);
        hi.y = __byte_perm(u2, u3, 0x7632);
        float r0 = v.x - __uint_as_float(u0 & 0xFFFF0000u);
        float r1 = v.y - __uint_as_float(u1 & 0xFFFF0000u);
        float r2 = v.z - __uint_as_float(u2 & 0xFFFF0000u);
        float r3 = v.w - __uint_as_float(u3 & 0xFFFF0000u);
        __nv_bfloat162 la = __float22bfloat162_rn(make_float2(r0, r1));
        __nv_bfloat162 lb = __float22bfloat162_rn(make_float2(r2, r3));
        lo.x = *(unsigned*)&la;
        lo.y = *(unsigned*)&lb;
        unsigned off = (unsigned)(c * 256) + (((unsigned)(l4 * 8)) ^ (((unsigned)c & 7u) << 4));
        *(uint2*)(smem + SM_XH + off) = hi;
        *(uint2*)(smem + SM_XL + off) = lo;
    }
    __syncthreads();

    unsigned acc0[5] = {0, 0, 0, 0, 0}, acc1[5] = {0, 0, 0, 0, 0};
    const int rr = lane & 15;
    const unsigned colb0 = (unsigned)((lane >> 4) * 16);

    for (int nt2 = 0; nt2 < 8; nt2++) {
        float C0[4] = {0.f, 0.f, 0.f, 0.f}, C1[4] = {0.f, 0.f, 0.f, 0.f};
        const unsigned colb = colb0 + (unsigned)(nt2 * 32);
#pragma unroll
        for (int s = 0; s < 8; s++) {
            int cc = s * 16 + rr;
            unsigned ba = (unsigned)(cc * 256) + (colb ^ (((unsigned)cc & 7u) << 4));
            unsigned bh0, bh1, bh2, bh3, bl0, bl1, bl2, bl3;
            LDSM_T(bh0, bh1, bh2, bh3, sXh + ba);
            LDSM_T(bl0, bl1, bl2, bl3, sXl + ba);
            MMA_BF16(C0, Ahi[s], bh0, bh1);
            MMA_BF16(C1, Ahi[s], bh2, bh3);
            MMA_BF16(C0, Ahi[s], bl0, bl1);
            MMA_BF16(C1, Ahi[s], bl2, bl3);
            MMA_BF16(C0, Alo[s], bh0, bh1);
            MMA_BF16(C1, Alo[s], bh2, bh3);
        }
#pragma unroll
        for (int half = 0; half < 2; half++) {
            const float* Cf = half ? C1 : C0;
            unsigned ja = bin_of(Cf[0], s0, c0b) * 21u + bin_of(Cf[1], s0, c0b);
            const uint4 ra = *(const uint4*)(tbl + ja * 8);
            unsigned ra4 = tbl[ja * 8 + 4];
            acc0[0] += ra.x; acc0[1] += ra.y; acc0[2] += ra.z; acc0[3] += ra.w; acc0[4] += ra4;
            unsigned jb = bin_of(Cf[2], s1, c1b) * 21u + bin_of(Cf[3], s1, c1b);
            const uint4 rb = *(const uint4*)(tbl + jb * 8);
            unsigned rb4 = tbl[jb * 8 + 4];
            acc1[0] += rb.x; acc1[1] += rb.y; acc1[2] += rb.z; acc1[3] += rb.w; acc1[4] += rb4;
        }
    }

#pragma unroll
    for (int k = 0; k < 5; k++) {
        acc0[k] += __shfl_xor_sync(0xFFFFFFFFu, acc0[k], 1);
        acc0[k] += __shfl_xor_sync(0xFFFFFFFFu, acc0[k], 2);
        acc1[k] += __shfl_xor_sync(0xFFFFFFFFu, acc1[k], 1);
        acc1[k] += __shfl_xor_sync(0xFFFFFFFFu, acc1[k], 2);
    }
    if ((lane & 3) == 0) {
        if (p0 < P_) {
            unsigned* d = g_chunk + ((size_t)(b * 128 + p0) * 5) * NLC + lc;
#pragma unroll
            for (int k = 0; k < 5; k++) d[k * NLC] = acc0[k];
        }
        if (p1 < P_) {
            unsigned* d = g_chunk + ((size_t)(b * 128 + p1) * 5) * NLC + lc;
#pragma unroll
            for (int k = 0; k < 5; k++) d[k * NLC] = acc1[k];
        }
    }
}

// ---------------------------------------------------------------------------
// Finalize: sum 32 chunk words per (b,p,w5) with SIMD byte-lane adds.
__global__ void finalize_kernel(float* __restrict__ out) {
    int i = blockIdx.x * 256 + threadIdx.x;
    if (i >= B_ * P_ * 5) return;
    int b = i / (P_ * 5), rem = i % (P_ * 5), p = rem / 5, w5 = rem % 5;
    const uint4* src = (const uint4*)(g_chunk + ((size_t)(b * 128 + p) * 5 + w5) * NLC);
    unsigned s01 = 0, s23 = 0;
#pragma unroll
    for (int k = 0; k < 8; k++) {
        uint4 v = src[k];
        s01 += (v.x & 0x00FF00FFu) + (v.y & 0x00FF00FFu) + (v.z & 0x00FF00FFu) + (v.w & 0x00FF00FFu);
        s23 += ((v.x >> 8) & 0x00FF00FFu) + ((v.y >> 8) & 0x00FF00FFu) +
               ((v.z >> 8) & 0x00FF00FFu) + ((v.w >> 8) & 0x00FF00FFu);
    }
    float* o = out + (size_t)b * (P_ * Q_) + p * Q_ + 4 * w5;
    const float inv = 1.0f / (float)L_;
    o[0] = (float)(s01 & 0xFFFFu) * inv;
    o[1] = (float)(s23 & 0xFFFFu) * inv;
    o[2] = (float)(s01 >> 16) * inv;
    o[3] = (float)(s23 >> 16) * inv;
}

// ---------------------------------------------------------------------------
extern "C" void kernel_launch(void* const* d_in, const int* in_sizes, int n_in,
                              void* d_out, int out_size) {
    const float* X    = (const float*)d_in[0];
    const float* W    = (const float*)d_in[1];
    const float* minv = (const float*)d_in[2];
    const float* maxv = (const float*)d_in[3];
    float* out = (float*)d_out;

    cudaFuncSetAttribute(radon_hmma, cudaFuncAttributeMaxDynamicSharedMemorySize, SM_TOTAL);

    prep_kernel<<<64, 256>>>(W);
    radon_hmma<<<B_ * NLC, 256, SM_TOTAL>>>(X, minv, maxv);
    finalize_kernel<<<(B_ * P_ * 5 + 255) / 256, 256>>>(out);
}

// round 6
// speedup vs baseline: 1.9225x; 1.0734x over previous
#include <cuda_runtime.h>
#include <cuda_fp16.h>
#include <cstdint>

#define B_   32
#define C_   128
#define L_   4096
#define P_   100
#define Q_   20
#define LG   512            // l per block
#define NLG  (L_ / LG)      // 8
#define NCH  4              // 128-l chunks per block
#define NG   (NLG * NCH)    // 32 store groups per (b,p)

#define SM_XH   0                       // 32768 B: fp16 [c(128)][l(128)]
#define SM_TBL  32768                   // 441*8*4 = 14112 B
#define SM_TOTAL (32768 + 441 * 32)     // 46880

// chunk scratch: [b][p(128)][w5(5)][g(32)] packed byte counters
__device__ unsigned g_chunk[B_ * 128 * 5 * NG];

__device__ __forceinline__ unsigned smem_u32(const void* p) {
    unsigned a;
    asm("{ .reg .u64 t; cvta.to.shared.u64 t, %1; cvt.u32.u64 %0, t; }" : "=r"(a) : "l"(p));
    return a;
}
#define LDSM_T(r0, r1, r2, r3, a) \
    asm volatile("ldmatrix.sync.aligned.m8n8.x4.trans.shared.b16 {%0,%1,%2,%3}, [%4];" \
                 : "=r"(r0), "=r"(r1), "=r"(r2), "=r"(r3) : "r"(a))
#define MMA_F16(Cv, Af, b0_, b1_) \
    asm volatile("mma.sync.aligned.m16n8k16.row.col.f32.f16.f16.f32 " \
                 "{%0,%1,%2,%3}, {%4,%5,%6,%7}, {%8,%9}, {%0,%1,%2,%3};" \
                 : "+f"((Cv)[0]), "+f"((Cv)[1]), "+f"((Cv)[2]), "+f"((Cv)[3]) \
                 : "r"((Af).x), "r"((Af).y), "r"((Af).z), "r"((Af).w), "r"(b0_), "r"(b1_))

// floor((a-mn)*s) clamped to [0,20] via magic-add (no F2I)
__device__ __forceinline__ unsigned bin_of(float a, float s, float bc) {
    float g = fminf(fmaxf(fmaf(a, s, bc), -0.5f), 19.99f);
    return __float_as_uint(__fadd_rn(g, 12582912.0f)) & 63u;
}
__device__ __forceinline__ unsigned h2bits(__half2 h) { return *(unsigned*)&h; }

// ---------------------------------------------------------------------------
extern __shared__ __align__(16) char smem[];

__global__ __launch_bounds__(256, 2)
void radon_hmma(const float* __restrict__ X,
                const float* __restrict__ W,
                const float* __restrict__ minv,
                const float* __restrict__ maxv) {
    const int tid = threadIdx.x, w = tid >> 5, lane = tid & 31;
    const int b = blockIdx.x >> 3, lg = blockIdx.x & 7;
    const unsigned sXh = smem_u32(smem);
    unsigned* tbl = (unsigned*)(smem + SM_TBL);

    // pair table: tbl[j1*21+j2][w5] bytes(q=4*w5+b4) = (q>=j1)+(q>=j2); stride 8
    for (int i = tid; i < 441 * 8; i += 256) {
        int row = i >> 3, w5 = i & 7;
        int j1 = row / 21, j2 = row % 21;
        unsigned v = 0;
        if (w5 < 5) {
#pragma unroll
            for (int b4 = 0; b4 < 4; b4++) {
                int q = 4 * w5 + b4;
                if (q < Q_) v |= (unsigned)((q >= j1) + (q >= j2)) << (8 * b4);
            }
        }
        tbl[i] = v;
    }

    // A fragments built directly from W (fp16 hi + lo split of fp32)
    const int r0 = w * 16 + (lane >> 2);
    const int r1 = r0 + 8;
    const int kp0 = 2 * (lane & 3);
    uint4 Ahi[8], Alo[8];
#pragma unroll
    for (int s = 0; s < 8; s++) {
        int kp = s * 16 + kp0;
        float2 a00 = (r0 < P_) ? *(const float2*)(W + r0 * C_ + kp)     : make_float2(0.f, 0.f);
        float2 a10 = (r1 < P_) ? *(const float2*)(W + r1 * C_ + kp)     : make_float2(0.f, 0.f);
        float2 a01 = (r0 < P_) ? *(const float2*)(W + r0 * C_ + kp + 8) : make_float2(0.f, 0.f);
        float2 a11 = (r1 < P_) ? *(const float2*)(W + r1 * C_ + kp + 8) : make_float2(0.f, 0.f);
        __half2 h00 = __float22half2_rn(a00), h10 = __float22half2_rn(a10);
        __half2 h01 = __float22half2_rn(a01), h11 = __float22half2_rn(a11);
        Ahi[s].x = h2bits(h00); Ahi[s].y = h2bits(h10);
        Ahi[s].z = h2bits(h01); Ahi[s].w = h2bits(h11);
        __half2 l00 = __float22half2_rn(make_float2(a00.x - __low2float(h00), a00.y - __high2float(h00)));
        __half2 l10 = __float22half2_rn(make_float2(a10.x - __low2float(h10), a10.y - __high2float(h10)));
        __half2 l01 = __float22half2_rn(make_float2(a01.x - __low2float(h01), a01.y - __high2float(h01)));
        __half2 l11 = __float22half2_rn(make_float2(a11.x - __low2float(h11), a11.y - __high2float(h11)));
        Alo[s].x = h2bits(l00); Alo[s].y = h2bits(l10);
        Alo[s].z = h2bits(l01); Alo[s].w = h2bits(l11);
    }

    const int p0 = r0, p1 = r1;
    float s0 = 0.f, c0b = 0.f, s1 = 0.f, c1b = 0.f;
    if (p0 < P_) { float mn = minv[p0]; s0 = 21.0f / (maxv[p0] - mn); c0b = -mn * s0 - 0.5f; }
    if (p1 < P_) { float mn = minv[p1]; s1 = 21.0f / (maxv[p1] - mn); c1b = -mn * s1 - 0.5f; }

    const int rr = lane & 15;
    const unsigned colb0 = (unsigned)((lane >> 4) * 16);
    const float* Xb = X + (size_t)b * C_ * L_ + lg * LG;

    for (int ch = 0; ch < NCH; ch++) {
        unsigned acc0[5] = {0, 0, 0, 0, 0}, acc1[5] = {0, 0, 0, 0, 0};

        // convert X chunk fp32 -> fp16, [c][l] rows (256B), 16B XOR swizzle
        const float* Xc = Xb + ch * 128;
#pragma unroll 4
        for (int it = 0; it < 16; it++) {
            int lin = it * 256 + tid;
            int c = lin >> 5, l4 = lin & 31;
            float4 v = *(const float4*)(Xc + (size_t)c * L_ + 4 * l4);
            __half2 h01 = __float22half2_rn(make_float2(v.x, v.y));
            __half2 h23 = __float22half2_rn(make_float2(v.z, v.w));
            unsigned off = (unsigned)(c * 256) + (((unsigned)(l4 * 8)) ^ (((unsigned)c & 7u) << 4));
            *(uint2*)(smem + off) = make_uint2(h2bits(h01), h2bits(h23));
        }
        __syncthreads();

        for (int nt2 = 0; nt2 < 8; nt2++) {
            float C0[4] = {0.f, 0.f, 0.f, 0.f}, C1[4] = {0.f, 0.f, 0.f, 0.f};
            const unsigned colb = colb0 + (unsigned)(nt2 * 32);
#pragma unroll
            for (int s = 0; s < 8; s++) {
                int cc = s * 16 + rr;
                unsigned ba = (unsigned)(cc * 256) + (colb ^ (((unsigned)cc & 7u) << 4));
                unsigned b0, b1, b2, b3;
                LDSM_T(b0, b1, b2, b3, sXh + ba);
                MMA_F16(C0, Ahi[s], b0, b1);
                MMA_F16(C1, Ahi[s], b2, b3);
                MMA_F16(C0, Alo[s], b0, b1);
                MMA_F16(C1, Alo[s], b2, b3);
            }
#pragma unroll
            for (int half = 0; half < 2; half++) {
                const float* Cf = half ? C1 : C0;
                unsigned ja = bin_of(Cf[0], s0, c0b) * 21u + bin_of(Cf[1], s0, c0b);
                const uint4 ra = *(const uint4*)(tbl + ja * 8);
                unsigned ra4 = tbl[ja * 8 + 4];
                acc0[0] += ra.x; acc0[1] += ra.y; acc0[2] += ra.z; acc0[3] += ra.w; acc0[4] += ra4;
                unsigned jb = bin_of(Cf[2], s1, c1b) * 21u + bin_of(Cf[3], s1, c1b);
                const uint4 rb = *(const uint4*)(tbl + jb * 8);
                unsigned rb4 = tbl[jb * 8 + 4];
                acc1[0] += rb.x; acc1[1] += rb.y; acc1[2] += rb.z; acc1[3] += rb.w; acc1[4] += rb4;
            }
        }
        __syncthreads();  // mainloop done before next conversion overwrites smem

        // flush EVERY chunk: pre-shuffle <=32 per byte, post-shuffle <=128 (no wrap)
#pragma unroll
        for (int k = 0; k < 5; k++) {
            acc0[k] += __shfl_xor_sync(0xFFFFFFFFu, acc0[k], 1);
            acc0[k] += __shfl_xor_sync(0xFFFFFFFFu, acc0[k], 2);
            acc1[k] += __shfl_xor_sync(0xFFFFFFFFu, acc1[k], 1);
            acc1[k] += __shfl_xor_sync(0xFFFFFFFFu, acc1[k], 2);
        }
        if ((lane & 3) == 0) {
            int g = lg * NCH + ch;
            if (p0 < P_) {
                unsigned* d = g_chunk + ((size_t)(b * 128 + p0) * 5) * NG + g;
#pragma unroll
                for (int k = 0; k < 5; k++) d[k * NG] = acc0[k];
            }
            if (p1 < P_) {
                unsigned* d = g_chunk + ((size_t)(b * 128 + p1) * 5) * NG + g;
#pragma unroll
                for (int k = 0; k < 5; k++) d[k * NG] = acc1[k];
            }
        }
    }
}

// ---------------------------------------------------------------------------
// Finalize: sum 32 chunk words per (b,p,w5) with SIMD byte-lane adds.
// 16-bit lanes max 32*128 = 4096 < 65536, safe.
__global__ void finalize_kernel(float* __restrict__ out) {
    int i = blockIdx.x * 256 + threadIdx.x;
    if (i >= B_ * P_ * 5) return;
    int b = i / (P_ * 5), rem = i % (P_ * 5), p = rem / 5, w5 = rem % 5;
    const uint4* src = (const uint4*)(g_chunk + ((size_t)(b * 128 + p) * 5 + w5) * NG);
    unsigned s01 = 0, s23 = 0;
#pragma unroll
    for (int k = 0; k < 8; k++) {
        uint4 v = src[k];
        s01 += (v.x & 0x00FF00FFu) + (v.y & 0x00FF00FFu) + (v.z & 0x00FF00FFu) + (v.w & 0x00FF00FFu);
        s23 += ((v.x >> 8) & 0x00FF00FFu) + ((v.y >> 8) & 0x00FF00FFu) +
               ((v.z >> 8) & 0x00FF00FFu) + ((v.w >> 8) & 0x00FF00FFu);
    }
    float* o = out + (size_t)b * (P_ * Q_) + p * Q_ + 4 * w5;
    const float inv = 1.0f / (float)L_;
    o[0] = (float)(s01 & 0xFFFFu) * inv;
    o[1] = (float)(s23 & 0xFFFFu) * inv;
    o[2] = (float)(s01 >> 16) * inv;
    o[3] = (float)(s23 >> 16) * inv;
}

// ---------------------------------------------------------------------------
extern "C" void kernel_launch(void* const* d_in, const int* in_sizes, int n_in,
                              void* d_out, int out_size) {
    const float* X    = (const float*)d_in[0];
    const float* W    = (const float*)d_in[1];
    const float* minv = (const float*)d_in[2];
    const float* maxv = (const float*)d_in[3];
    float* out = (float*)d_out;

    cudaFuncSetAttribute(radon_hmma, cudaFuncAttributeMaxDynamicSharedMemorySize, SM_TOTAL);

    radon_hmma<<<B_ * NLG, 256, SM_TOTAL>>>(X, W, minv, maxv);
    finalize_kernel<<<(B_ * P_ * 5 + 255) / 256, 256>>>(out);
}

// round 7
// speedup vs baseline: 1.9958x; 1.0381x over previous
#include <cuda_runtime.h>
#include <cuda_fp16.h>
#include <cstdint>

#define B_   32
#define C_   128
#define L_   4096
#define P_   100
#define Q_   20
#define LG   256            // l per block
#define NLG  (L_ / LG)      // 16
#define NCH  2              // 128-l chunks per block
#define NG   (NLG * NCH)    // 32 store groups per (b,p)

#define SM_XH   0                       // 32768 B: fp16 [c(128)][l(128)]
#define SM_TBL  32768                   // 441*8*4 = 14112 B
#define SM_TOTAL (32768 + 441 * 32)     // 46880

// chunk scratch: [b][p(128)][w5(5)][g(32)] packed byte counters
__device__ unsigned g_chunk[B_ * 128 * 5 * NG];

__device__ __forceinline__ unsigned smem_u32(const void* p) {
    unsigned a;
    asm("{ .reg .u64 t; cvta.to.shared.u64 t, %1; cvt.u32.u64 %0, t; }" : "=r"(a) : "l"(p));
    return a;
}
#define LDSM_T(r0, r1, r2, r3, a) \
    asm volatile("ldmatrix.sync.aligned.m8n8.x4.trans.shared.b16 {%0,%1,%2,%3}, [%4];" \
                 : "=r"(r0), "=r"(r1), "=r"(r2), "=r"(r3) : "r"(a))
#define MMA_F16(Cv, Af, b0_, b1_) \
    asm volatile("mma.sync.aligned.m16n8k16.row.col.f32.f16.f16.f32 " \
                 "{%0,%1,%2,%3}, {%4,%5,%6,%7}, {%8,%9}, {%0,%1,%2,%3};" \
                 : "+f"((Cv)[0]), "+f"((Cv)[1]), "+f"((Cv)[2]), "+f"((Cv)[3]) \
                 : "r"((Af).x), "r"((Af).y), "r"((Af).z), "r"((Af).w), "r"(b0_), "r"(b1_))

// floor((a-mn)*s) clamped to [0,20] via magic-add (no F2I)
__device__ __forceinline__ unsigned bin_of(float a, float s, float bc) {
    float g = fminf(fmaxf(fmaf(a, s, bc), -0.5f), 19.99f);
    return __float_as_uint(__fadd_rn(g, 12582912.0f)) & 63u;
}
__device__ __forceinline__ unsigned h2bits(__half2 h) { return *(unsigned*)&h; }

// ---------------------------------------------------------------------------
extern __shared__ __align__(16) char smem[];

__global__ __launch_bounds__(256, 2)
void radon_hmma(const float* __restrict__ X,
                const float* __restrict__ W,
                const float* __restrict__ minv,
                const float* __restrict__ maxv) {
    const int tid = threadIdx.x, w = tid >> 5, lane = tid & 31;
    const int b = blockIdx.x >> 4, lg = blockIdx.x & 15;
    const unsigned sXh = smem_u32(smem);
    unsigned* tbl = (unsigned*)(smem + SM_TBL);

    // pair table: tbl[j1*21+j2][w5] bytes(q=4*w5+b4) = (q>=j1)+(q>=j2); stride 8
    for (int i = tid; i < 441 * 8; i += 256) {
        int row = i >> 3, w5 = i & 7;
        int j1 = row / 21, j2 = row % 21;
        unsigned v = 0;
        if (w5 < 5) {
#pragma unroll
            for (int b4 = 0; b4 < 4; b4++) {
                int q = 4 * w5 + b4;
                if (q < Q_) v |= (unsigned)((q >= j1) + (q >= j2)) << (8 * b4);
            }
        }
        tbl[i] = v;
    }

    // A fragments built directly from W (single rn fp16)
    const int r0 = w * 16 + (lane >> 2);
    const int r1 = r0 + 8;
    const int kp0 = 2 * (lane & 3);
    uint4 Ahi[8];
#pragma unroll
    for (int s = 0; s < 8; s++) {
        int kp = s * 16 + kp0;
        float2 a00 = (r0 < P_) ? *(const float2*)(W + r0 * C_ + kp)     : make_float2(0.f, 0.f);
        float2 a10 = (r1 < P_) ? *(const float2*)(W + r1 * C_ + kp)     : make_float2(0.f, 0.f);
        float2 a01 = (r0 < P_) ? *(const float2*)(W + r0 * C_ + kp + 8) : make_float2(0.f, 0.f);
        float2 a11 = (r1 < P_) ? *(const float2*)(W + r1 * C_ + kp + 8) : make_float2(0.f, 0.f);
        Ahi[s].x = h2bits(__float22half2_rn(a00));
        Ahi[s].y = h2bits(__float22half2_rn(a10));
        Ahi[s].z = h2bits(__float22half2_rn(a01));
        Ahi[s].w = h2bits(__float22half2_rn(a11));
    }

    const int p0 = r0, p1 = r1;
    float s0 = 0.f, c0b = 0.f, s1 = 0.f, c1b = 0.f;
    if (p0 < P_) { float mn = minv[p0]; s0 = 21.0f / (maxv[p0] - mn); c0b = -mn * s0 - 0.5f; }
    if (p1 < P_) { float mn = minv[p1]; s1 = 21.0f / (maxv[p1] - mn); c1b = -mn * s1 - 0.5f; }

    const int rr = lane & 15;
    const unsigned colb0 = (unsigned)((lane >> 4) * 16);
    const float* Xb = X + (size_t)b * C_ * L_ + lg * LG;

    for (int ch = 0; ch < NCH; ch++) {
        unsigned acc0[5] = {0, 0, 0, 0, 0}, acc1[5] = {0, 0, 0, 0, 0};

        // convert X chunk fp32 -> fp16, [c][l] rows (256B), 16B XOR swizzle
        const float* Xc = Xb + ch * 128;
#pragma unroll 4
        for (int it = 0; it < 16; it++) {
            int lin = it * 256 + tid;
            int c = lin >> 5, l4 = lin & 31;
            float4 v = *(const float4*)(Xc + (size_t)c * L_ + 4 * l4);
            __half2 h01 = __float22half2_rn(make_float2(v.x, v.y));
            __half2 h23 = __float22half2_rn(make_float2(v.z, v.w));
            unsigned off = (unsigned)(c * 256) + (((unsigned)(l4 * 8)) ^ (((unsigned)c & 7u) << 4));
            *(uint2*)(smem + off) = make_uint2(h2bits(h01), h2bits(h23));
        }
        __syncthreads();

        for (int nt2 = 0; nt2 < 8; nt2++) {
            float C0[4] = {0.f, 0.f, 0.f, 0.f}, C1[4] = {0.f, 0.f, 0.f, 0.f};
            const unsigned colb = colb0 + (unsigned)(nt2 * 32);
#pragma unroll
            for (int s = 0; s < 8; s++) {
                int cc = s * 16 + rr;
                unsigned ba = (unsigned)(cc * 256) + (colb ^ (((unsigned)cc & 7u) << 4));
                unsigned b0, b1, b2, b3;
                LDSM_T(b0, b1, b2, b3, sXh + ba);
                MMA_F16(C0, Ahi[s], b0, b1);
                MMA_F16(C1, Ahi[s], b2, b3);
            }
#pragma unroll
            for (int half = 0; half < 2; half++) {
                const float* Cf = half ? C1 : C0;
                unsigned ja = bin_of(Cf[0], s0, c0b) * 21u + bin_of(Cf[1], s0, c0b);
                const uint4 ra = *(const uint4*)(tbl + ja * 8);
                unsigned ra4 = tbl[ja * 8 + 4];
                acc0[0] += ra.x; acc0[1] += ra.y; acc0[2] += ra.z; acc0[3] += ra.w; acc0[4] += ra4;
                unsigned jb = bin_of(Cf[2], s1, c1b) * 21u + bin_of(Cf[3], s1, c1b);
                const uint4 rb = *(const uint4*)(tbl + jb * 8);
                unsigned rb4 = tbl[jb * 8 + 4];
                acc1[0] += rb.x; acc1[1] += rb.y; acc1[2] += rb.z; acc1[3] += rb.w; acc1[4] += rb4;
            }
        }
        __syncthreads();  // mainloop done before next conversion overwrites smem

        // flush every chunk: pre-shuffle <=32 per byte, post-shuffle <=128
#pragma unroll
        for (int k = 0; k < 5; k++) {
            acc0[k] += __shfl_xor_sync(0xFFFFFFFFu, acc0[k], 1);
            acc0[k] += __shfl_xor_sync(0xFFFFFFFFu, acc0[k], 2);
            acc1[k] += __shfl_xor_sync(0xFFFFFFFFu, acc1[k], 1);
            acc1[k] += __shfl_xor_sync(0xFFFFFFFFu, acc1[k], 2);
        }
        if ((lane & 3) == 0) {
            int g = lg * NCH + ch;
            if (p0 < P_) {
                unsigned* d = g_chunk + ((size_t)(b * 128 + p0) * 5) * NG + g;
#pragma unroll
                for (int k = 0; k < 5; k++) d[k * NG] = acc0[k];
            }
            if (p1 < P_) {
                unsigned* d = g_chunk + ((size_t)(b * 128 + p1) * 5) * NG + g;
#pragma unroll
                for (int k = 0; k < 5; k++) d[k * NG] = acc1[k];
            }
        }
    }
}

// ---------------------------------------------------------------------------
// Finalize: sum 32 chunk words per (b,p,w5) with SIMD byte-lane adds.
// 16-bit lanes max 32*128 = 4096 < 65536, safe.
__global__ void finalize_kernel(float* __restrict__ out) {
    int i = blockIdx.x * 256 + threadIdx.x;
    if (i >= B_ * P_ * 5) return;
    int b = i / (P_ * 5), rem = i % (P_ * 5), p = rem / 5, w5 = rem % 5;
    const uint4* src = (const uint4*)(g_chunk + ((size_t)(b * 128 + p) * 5 + w5) * NG);
    unsigned s01 = 0, s23 = 0;
#pragma unroll
    for (int k = 0; k < 8; k++) {
        uint4 v = src[k];
        s01 += (v.x & 0x00FF00FFu) + (v.y & 0x00FF00FFu) + (v.z & 0x00FF00FFu) + (v.w & 0x00FF00FFu);
        s23 += ((v.x >> 8) & 0x00FF00FFu) + ((v.y >> 8) & 0x00FF00FFu) +
               ((v.z >> 8) & 0x00FF00FFu) + ((v.w >> 8) & 0x00FF00FFu);
    }
    float* o = out + (size_t)b * (P_ * Q_) + p * Q_ + 4 * w5;
    const float inv = 1.0f / (float)L_;
    o[0] = (float)(s01 & 0xFFFFu) * inv;
    o[1] = (float)(s23 & 0xFFFFu) * inv;
    o[2] = (float)(s01 >> 16) * inv;
    o[3] = (float)(s23 >> 16) * inv;
}

// ---------------------------------------------------------------------------
extern "C" void kernel_launch(void* const* d_in, const int* in_sizes, int n_in,
                              void* d_out, int out_size) {
    const float* X    = (const float*)d_in[0];
    const float* W    = (const float*)d_in[1];
    const float* minv = (const float*)d_in[2];
    const float* maxv = (const float*)d_in[3];
    float* out = (float*)d_out;

    cudaFuncSetAttribute(radon_hmma, cudaFuncAttributeMaxDynamicSharedMemorySize, SM_TOTAL);

    radon_hmma<<<B_ * NLG, 256, SM_TOTAL>>>(X, W, minv, maxv);
    finalize_kernel<<<(B_ * P_ * 5 + 255) / 256, 256>>>(out);
}